// round 10
// baseline (speedup 1.0000x reference)
#include <cuda_runtime.h>
#include <cstdint>

// AudioDeviceModel_89008902242543  — R9
//
// s[b]      = dot(x[b,:], w1[0,:,0]) + b1+b2+b3+b4+b5
// out[b,d]  = s[b]*wd[d] + bd[d]            (B=8192, L=16384, D=128)
//
// HBM-read-bound (512 MB of x). Register-MLP path plateaued at 86.6%
// DRAM (R6). R9: cp.async.bulk -> smem ring pipeline. A single elected
// thread streams 8 KB bulk copies (5-stage ring, 40 KB in flight/CTA,
// 160 KB/SM) so DRAM request issue is decoupled from warp scheduling;
// consumers do LDS.128 + FMA. Grid shape = R6's proven 4096/occ4.

#define B_ROWS  8192
#define L_COLS  16384
#define RPB     2
#define NT      256
#define NWARPS  (NT / 32)
#define CHUNK   2048                  // floats per stage = 8 KB
#define CHUNK4  (CHUNK / 4)           // 512 float4
#define NCHUNK  (L_COLS / CHUNK)      // 8 chunks per row
#define NJOBS   (RPB * NCHUNK)        // 16 jobs per CTA
#define NSTAGE  5                     // ring depth (40 KB data smem)
#define STAGE_BYTES (CHUNK * 4)       // 8192

__device__ __forceinline__ uint32_t smem_u32(const void* p) {
    uint32_t a;
    asm("{ .reg .u64 t; cvta.to.shared.u64 t, %1; cvt.u32.u64 %0, t; }"
        : "=r"(a) : "l"(p));
    return a;
}

__device__ __forceinline__ void mbar_init(uint32_t mbar, uint32_t count) {
    asm volatile("mbarrier.init.shared.b64 [%0], %1;" :: "r"(mbar), "r"(count) : "memory");
}

__device__ __forceinline__ void mbar_expect_tx(uint32_t mbar, uint32_t bytes) {
    asm volatile("mbarrier.arrive.expect_tx.shared.b64 _, [%0], %1;"
                 :: "r"(mbar), "r"(bytes) : "memory");
}

__device__ __forceinline__ void mbar_arrive(uint32_t mbar) {
    asm volatile("mbarrier.arrive.shared.b64 _, [%0];" :: "r"(mbar) : "memory");
}

// Acquire wait (consumer side: generic LDS reads follow).
__device__ __forceinline__ void mbar_wait(uint32_t mbar, uint32_t parity) {
    uint32_t done;
    asm volatile(
        "{\n\t.reg .pred p;\n\t"
        "mbarrier.try_wait.parity.acquire.cta.shared::cta.b64 p, [%1], %2;\n\t"
        "selp.b32 %0, 1, 0, p;\n\t}"
        : "=r"(done) : "r"(mbar), "r"(parity) : "memory");
    if (!done) {
        asm volatile(
            "{\n\t.reg .pred P1;\n\t"
            "W_%=:\n\t"
            "mbarrier.try_wait.parity.acquire.cta.shared::cta.b64 P1, [%0], %1, 0x989680;\n\t"
            "@P1 bra.uni D_%=;\n\t"
            "bra.uni W_%=;\n\t"
            "D_%=:\n\t}"
            :: "r"(mbar), "r"(parity) : "memory");
    }
}

// 1D bulk async copy global -> shared::cta, completion via mbarrier tx.
__device__ __forceinline__ void bulk_g2s(uint32_t dst_smem, const void* src_gmem,
                                         uint32_t bytes, uint32_t mbar) {
    asm volatile(
        "cp.async.bulk.shared::cta.global.mbarrier::complete_tx::bytes "
        "[%0], [%1], %2, [%3];"
        :: "r"(dst_smem), "l"(src_gmem), "r"(bytes), "r"(mbar) : "memory");
}

__device__ __forceinline__ float dot4_acc(float4 xx, float4 w, float a) {
    return fmaf(xx.x, w.x, fmaf(xx.y, w.y, fmaf(xx.z, w.z, fmaf(xx.w, w.w, a))));
}

__global__ __launch_bounds__(NT, 4)
void audio_model_kernel(const float* __restrict__ x,
                        const float* __restrict__ w1,
                        const float* __restrict__ b1,
                        const float* __restrict__ b2,
                        const float* __restrict__ b3,
                        const float* __restrict__ b4,
                        const float* __restrict__ b5,
                        const float* __restrict__ wd,
                        const float* __restrict__ bd,
                        float* __restrict__ out)
{
    __shared__ __align__(16) float sdata[NSTAGE * CHUNK];   // 40 KB
    __shared__ uint64_t mb_full[NSTAGE];
    __shared__ uint64_t mb_empty[NSTAGE];
    __shared__ float part[NWARPS][RPB];
    __shared__ float srow[RPB];

    const int tid = threadIdx.x;
    const int wid = tid >> 5;
    const int lid = tid & 31;
    const int b0  = blockIdx.x * RPB;

    const uint32_t full_a  = smem_u32(mb_full);
    const uint32_t empty_a = smem_u32(mb_empty);
    const uint32_t data_a  = smem_u32(sdata);

    if (tid == 0) {
#pragma unroll
        for (int s = 0; s < NSTAGE; s++) {
            mbar_init(full_a + 8u * s, 1);       // expect_tx arrival
            mbar_init(empty_a + 8u * s, NT);     // all threads arrive
        }
    }
    __syncthreads();

    const float4* __restrict__ wv  = reinterpret_cast<const float4*>(w1);
    const float4* __restrict__ sd4 = reinterpret_cast<const float4*>(sdata);

    float acc[RPB];
#pragma unroll
    for (int r = 0; r < RPB; r++) acc[r] = 0.0f;

    // Consumer cursor (phase 0) / producer cursor (phase 1: first empty-
    // waits pass immediately on freshly-initialized barriers).
    int cs = 0, cp = 0;
    int ps = 0, pp = 1;
    int pj = 0;   // next job to issue (tid 0 only)

#pragma unroll 1
    for (int j = 0; j < NJOBS; ++j) {
        // Producer: keep up to NSTAGE-1 jobs ahead of the consume point.
        if (tid == 0) {
            while (pj < NJOBS && pj < j + NSTAGE) {
                mbar_wait(empty_a + 8u * ps, (uint32_t)pp);
                mbar_expect_tx(full_a + 8u * ps, STAGE_BYTES);
                const float* src = x + (size_t)(b0 + (pj >> 3)) * L_COLS
                                     + (size_t)(pj & 7) * CHUNK;
                bulk_g2s(data_a + (uint32_t)ps * STAGE_BYTES, src,
                         STAGE_BYTES, full_a + 8u * ps);
                ++pj;
                if (++ps == NSTAGE) { ps = 0; pp ^= 1; }
            }
        }

        // Consume job j from slot cs.
        mbar_wait(full_a + 8u * cs, (uint32_t)cp);

        const int c = j & 7;           // w-chunk index
        float4 x0 = sd4[cs * CHUNK4 + tid * 2];
        float4 x1 = sd4[cs * CHUNK4 + tid * 2 + 1];
        float4 w0 = wv[c * CHUNK4 + tid * 2];
        float4 w1v = wv[c * CHUNK4 + tid * 2 + 1];

        float a = dot4_acc(x1, w1v, dot4_acc(x0, w0, 0.0f));
        if (j < NCHUNK) acc[0] += a; else acc[1] += a;

        mbar_arrive(empty_a + 8u * cs);
        if (++cs == NSTAGE) { cs = 0; cp ^= 1; }
    }

    // Intra-warp tree reduction for each row accumulator.
#pragma unroll
    for (int r = 0; r < RPB; r++) {
#pragma unroll
        for (int off = 16; off > 0; off >>= 1)
            acc[r] += __shfl_xor_sync(0xffffffffu, acc[r], off);
    }

    if (lid == 0) {
#pragma unroll
        for (int r = 0; r < RPB; r++) part[wid][r] = acc[r];
    }
    __syncthreads();

    if (tid < RPB) {
        float s = 0.0f;
#pragma unroll
        for (int w = 0; w < NWARPS; w++) s += part[w][tid];
        srow[tid] = s + b1[0] + b2[0] + b3[0] + b4[0] + b5[0];
    }
    __syncthreads();

    // Epilogue: 2 rows x 128 outputs, coalesced.
#pragma unroll
    for (int jj = tid; jj < RPB * 128; jj += NT) {
        const int r = jj >> 7;
        const int d = jj & 127;
        out[(size_t)(b0 + r) * 128 + d] = fmaf(srow[r], wd[d], bd[d]);
    }
}

extern "C" void kernel_launch(void* const* d_in, const int* in_sizes, int n_in,
                              void* d_out, int out_size)
{
    // metadata order: x, w1, b1, w2, b2, w3, b3, w4, b4, w5, b5, wd, bd
    const float* x  = (const float*)d_in[0];
    const float* w1 = (const float*)d_in[1];
    const float* b1 = (const float*)d_in[2];
    const float* b2 = (const float*)d_in[4];
    const float* b3 = (const float*)d_in[6];
    const float* b4 = (const float*)d_in[8];
    const float* b5 = (const float*)d_in[10];
    const float* wd = (const float*)d_in[11];
    const float* bd = (const float*)d_in[12];
    float* out = (float*)d_out;

    dim3 grid(B_ROWS / RPB);   // 4096 CTAs
    audio_model_kernel<<<grid, NT>>>(x, w1, b1, b2, b3, b4, b5, wd, bd, out);
}

// round 11
// speedup vs baseline: 1.0044x; 1.0044x over previous
#include <cuda_runtime.h>
#include <cstdint>

// AudioDeviceModel_89008902242543  — R10
//
// s[b]      = dot(x[b,:], w1[0,:,0]) + b1+b2+b3+b4+b5
// out[b,d]  = s[b]*wd[d] + bd[d]            (B=8192, L=16384, D=128)
//
// HBM-read-bound (512 MB of x). R9's cp.async.bulk pipeline failed on
// CTA-wide mbarrier overhead (alu 20%, issue 30%). R10: WARP-PRIVATE
// 2-stage rings — each warp owns a 2048-float column slice of the 2
// rows, produces (lane0 bulk + expect_tx) and consumes (acquire
// try_wait + LDS.128) its own ring. No empty barriers, no CTA syncs in
// the mainloop; ring reuse is same-warp program order + proxy fence.
// Grid = R6's proven 4096 CTAs / occ 4.

#define B_ROWS  8192
#define L_COLS  16384
#define RPB     2
#define NT      256
#define NWARPS  (NT / 32)
#define WCOLS   (L_COLS / NWARPS)   // 2048 floats per row per warp
#define PIECE   512                 // floats per job (2 KB)
#define PIECE4  (PIECE / 4)         // 128 float4
#define NPIECE  (WCOLS / PIECE)     // 4 pieces per row
#define NJOBS   (RPB * NPIECE)      // 8 jobs per warp
#define NSTG    2                   // warp-private ring depth
#define STG_BYTES (PIECE * 4)       // 2048

__device__ __forceinline__ uint32_t smem_u32(const void* p) {
    uint32_t a;
    asm("{ .reg .u64 t; cvta.to.shared.u64 t, %1; cvt.u32.u64 %0, t; }"
        : "=r"(a) : "l"(p));
    return a;
}

__device__ __forceinline__ void mbar_init(uint32_t mbar, uint32_t count) {
    asm volatile("mbarrier.init.shared.b64 [%0], %1;" :: "r"(mbar), "r"(count) : "memory");
}

__device__ __forceinline__ void mbar_expect_tx(uint32_t mbar, uint32_t bytes) {
    asm volatile("mbarrier.arrive.expect_tx.shared.b64 _, [%0], %1;"
                 :: "r"(mbar), "r"(bytes) : "memory");
}

// Acquire wait (generic LDS reads follow).
__device__ __forceinline__ void mbar_wait(uint32_t mbar, uint32_t parity) {
    uint32_t done;
    asm volatile(
        "{\n\t.reg .pred p;\n\t"
        "mbarrier.try_wait.parity.acquire.cta.shared::cta.b64 p, [%1], %2;\n\t"
        "selp.b32 %0, 1, 0, p;\n\t}"
        : "=r"(done) : "r"(mbar), "r"(parity) : "memory");
    if (!done) {
        asm volatile(
            "{\n\t.reg .pred P1;\n\t"
            "W_%=:\n\t"
            "mbarrier.try_wait.parity.acquire.cta.shared::cta.b64 P1, [%0], %1, 0x989680;\n\t"
            "@P1 bra.uni D_%=;\n\t"
            "bra.uni W_%=;\n\t"
            "D_%=:\n\t}"
            :: "r"(mbar), "r"(parity) : "memory");
    }
}

__device__ __forceinline__ void fence_proxy_async_cta() {
    asm volatile("fence.proxy.async.shared::cta;" ::: "memory");
}

// 1D bulk async copy global -> shared::cta, completion via mbarrier tx.
__device__ __forceinline__ void bulk_g2s(uint32_t dst_smem, const void* src_gmem,
                                         uint32_t bytes, uint32_t mbar) {
    asm volatile(
        "cp.async.bulk.shared::cta.global.mbarrier::complete_tx::bytes "
        "[%0], [%1], %2, [%3];"
        :: "r"(dst_smem), "l"(src_gmem), "r"(bytes), "r"(mbar) : "memory");
}

__device__ __forceinline__ float dot4_acc(float4 xx, float4 w, float a) {
    return fmaf(xx.x, w.x, fmaf(xx.y, w.y, fmaf(xx.z, w.z, fmaf(xx.w, w.w, a))));
}

__global__ __launch_bounds__(NT, 4)
void audio_model_kernel(const float* __restrict__ x,
                        const float* __restrict__ w1,
                        const float* __restrict__ b1,
                        const float* __restrict__ b2,
                        const float* __restrict__ b3,
                        const float* __restrict__ b4,
                        const float* __restrict__ b5,
                        const float* __restrict__ wd,
                        const float* __restrict__ bd,
                        float* __restrict__ out)
{
    __shared__ __align__(16) float sdata[NWARPS * NSTG * PIECE];   // 32 KB
    __shared__ uint64_t mbar[NWARPS * NSTG];
    __shared__ float part[NWARPS][RPB];
    __shared__ float srow[RPB];

    const int tid = threadIdx.x;
    const int wid = tid >> 5;
    const int lid = tid & 31;
    const int b0  = blockIdx.x * RPB;

    const uint32_t mbar_a = smem_u32(mbar);
    const uint32_t data_a = smem_u32(sdata);

    if (tid == 0) {
#pragma unroll
        for (int s = 0; s < NWARPS * NSTG; s++)
            mbar_init(mbar_a + 8u * s, 1);   // single expect_tx arrival
    }
    __syncthreads();

    // Warp-private ring base addresses.
    const uint32_t my_mbar = mbar_a + (uint32_t)(wid * NSTG) * 8u;
    const uint32_t my_data = data_a + (uint32_t)(wid * NSTG) * STG_BYTES;

    // Warp's GMEM column base (floats) within each row.
    const float* row0 = x + (size_t)b0 * L_COLS + wid * WCOLS;

    const float4* __restrict__ wv  = reinterpret_cast<const float4*>(w1);
    const float4* __restrict__ sd4 =
        reinterpret_cast<const float4*>(sdata) + (size_t)wid * NSTG * PIECE4;

    // Job j (0..7): row r = j>>2, piece p = j&3.
    //   src  = row0 + r*L_COLS + p*PIECE
    //   ring slot = j & 1, wait parity = (j>>1) & 1
    float acc[RPB];
    acc[0] = 0.0f; acc[1] = 0.0f;

    // Prologue: issue jobs 0 and 1.
    if (lid == 0) {
#pragma unroll
        for (int j = 0; j < NSTG; j++) {
            mbar_expect_tx(my_mbar + 8u * j, STG_BYTES);
            bulk_g2s(my_data + (uint32_t)j * STG_BYTES,
                     row0 + (size_t)(j >> 2) * L_COLS + (j & 3) * PIECE,
                     STG_BYTES, my_mbar + 8u * j);
        }
    }

#pragma unroll 1
    for (int j = 0; j < NJOBS; ++j) {
        const int s = j & 1;
        mbar_wait(my_mbar + 8u * s, (uint32_t)((j >> 1) & 1));

        // Consume 2 KB: 4 LDS.128 + 4 w loads (L1/L2-resident) + 16 FMA.
        const int p = j & 3;
        const int wbase = wid * (WCOLS / 4) + p * PIECE4;   // float4 idx in w
        float a = 0.0f;
#pragma unroll
        for (int k = 0; k < 4; k++) {
            float4 xx = sd4[s * PIECE4 + lid + 32 * k];
            float4 ww = wv[wbase + lid + 32 * k];
            a = dot4_acc(xx, ww, a);
        }
        acc[j >> 2] += a;

        // Refill this slot with job j+NSTG (same warp: reads above are
        // program-order complete; fence orders generic reads vs async write).
        const int jn = j + NSTG;
        if (jn < NJOBS && lid == 0) {
            fence_proxy_async_cta();
            mbar_expect_tx(my_mbar + 8u * s, STG_BYTES);
            bulk_g2s(my_data + (uint32_t)s * STG_BYTES,
                     row0 + (size_t)(jn >> 2) * L_COLS + (jn & 3) * PIECE,
                     STG_BYTES, my_mbar + 8u * s);
        }
    }

    // Intra-warp tree reduction (each warp holds partial dots of its slice).
#pragma unroll
    for (int r = 0; r < RPB; r++) {
#pragma unroll
        for (int off = 16; off > 0; off >>= 1)
            acc[r] += __shfl_xor_sync(0xffffffffu, acc[r], off);
    }

    if (lid == 0) {
#pragma unroll
        for (int r = 0; r < RPB; r++) part[wid][r] = acc[r];
    }
    __syncthreads();

    if (tid < RPB) {
        float s = 0.0f;
#pragma unroll
        for (int w = 0; w < NWARPS; w++) s += part[w][tid];
        srow[tid] = s + b1[0] + b2[0] + b3[0] + b4[0] + b5[0];
    }
    __syncthreads();

    // Epilogue: 2 rows x 128 outputs, coalesced.
#pragma unroll
    for (int jj = tid; jj < RPB * 128; jj += NT) {
        const int r = jj >> 7;
        const int d = jj & 127;
        out[(size_t)(b0 + r) * 128 + d] = fmaf(srow[r], wd[d], bd[d]);
    }
}

extern "C" void kernel_launch(void* const* d_in, const int* in_sizes, int n_in,
                              void* d_out, int out_size)
{
    // metadata order: x, w1, b1, w2, b2, w3, b3, w4, b4, w5, b5, wd, bd
    const float* x  = (const float*)d_in[0];
    const float* w1 = (const float*)d_in[1];
    const float* b1 = (const float*)d_in[2];
    const float* b2 = (const float*)d_in[4];
    const float* b3 = (const float*)d_in[6];
    const float* b4 = (const float*)d_in[8];
    const float* b5 = (const float*)d_in[10];
    const float* wd = (const float*)d_in[11];
    const float* bd = (const float*)d_in[12];
    float* out = (float*)d_out;

    dim3 grid(B_ROWS / RPB);   // 4096 CTAs
    audio_model_kernel<<<grid, NT>>>(x, w1, b1, b2, b3, b4, b5, wd, bd, out);
}

// round 12
// speedup vs baseline: 1.1580x; 1.1528x over previous
#include <cuda_runtime.h>

// AudioDeviceModel_89008902242543  — R11
//
// s[b]      = dot(x[b,:], w1[0,:,0]) + b1+b2+b3+b4+b5
// out[b,d]  = s[b]*wd[d] + bd[d]            (B=8192, L=16384, D=128)
//
// HBM-read-bound (512 MB of x). Async bulk paths disproven (R9/R10).
// R6's residual ~13% is the ramp-down tail (T_CTA ~ 11.4us). R11:
// split-K — each CTA does a HALF row-pair (2 rows x 8192 cols), grid
// 8192, T_CTA ~ 5.7us, partials to __device__ scratch (slot per split,
// deterministic). Tiny epilogue kernel sums partials + bias and applies
// wd/bd. Inner loop = R6's proven 8-LDG front-batch; w-LDG rate and
// L2 traffic unchanged vs R6.

#define B_ROWS  8192
#define L_COLS  16384
#define L4      (L_COLS / 4)    // 4096 float4 per row
#define RPB     2               // rows per CTA
#define SPLIT   2               // column splits per row-pair
#define L4S     (L4 / SPLIT)    // 2048 float4 per split
#define NT      256
#define NWARPS  (NT / 32)
#define UNR     4               // column steps per batch
#define ITERS   (L4S / NT)      // 8 -> 2 batches of UNR

__device__ float g_partial[B_ROWS * SPLIT];

__device__ __forceinline__ float dot4_acc(float4 xx, float4 w, float a) {
    return fmaf(xx.x, w.x, fmaf(xx.y, w.y, fmaf(xx.z, w.z, fmaf(xx.w, w.w, a))));
}

__global__ __launch_bounds__(NT, 4)
void audio_dot_kernel(const float* __restrict__ x,
                      const float* __restrict__ w1)
{
    // blockIdx.x in [0, (B_ROWS/RPB)*SPLIT)
    const int pair  = blockIdx.x >> 1;       // row-pair index
    const int split = blockIdx.x & 1;        // column half
    const int b0    = pair * RPB;
    const int tid   = threadIdx.x;

    const float4* __restrict__ wv = reinterpret_cast<const float4*>(w1);
    const float4* __restrict__ xv =
        reinterpret_cast<const float4*>(x) + (size_t)b0 * L4;

    const int col0 = split * L4S;

    float acc[RPB];
#pragma unroll
    for (int r = 0; r < RPB; r++) acc[r] = 0.0f;

    int i = col0 + tid;
#pragma unroll 1
    for (int it = 0; it < ITERS; it += UNR, i += UNR * NT) {
        // Front-batch the 8 HBM loads (2 rows x 4 column steps).
        float4 xx[RPB][UNR];
#pragma unroll
        for (int u = 0; u < UNR; u++)
#pragma unroll
            for (int r = 0; r < RPB; r++)
                xx[r][u] = __ldcs(&xv[(size_t)r * L4 + i + u * NT]);

        // w loads are L2 hits; JIT to save registers.
#pragma unroll
        for (int u = 0; u < UNR; u++) {
            float4 w = wv[i + u * NT];
#pragma unroll
            for (int r = 0; r < RPB; r++)
                acc[r] = dot4_acc(xx[r][u], w, acc[r]);
        }
    }

    // Intra-warp tree reduction for each row accumulator.
#pragma unroll
    for (int r = 0; r < RPB; r++) {
#pragma unroll
        for (int off = 16; off > 0; off >>= 1)
            acc[r] += __shfl_xor_sync(0xffffffffu, acc[r], off);
    }

    __shared__ float part[NWARPS][RPB];
    const int wid = tid >> 5;
    const int lid = tid & 31;
    if (lid == 0) {
#pragma unroll
        for (int r = 0; r < RPB; r++) part[wid][r] = acc[r];
    }
    __syncthreads();

    if (tid < RPB) {
        float s = 0.0f;
#pragma unroll
        for (int w = 0; w < NWARPS; w++) s += part[w][tid];
        g_partial[(b0 + tid) * SPLIT + split] = s;   // deterministic slot
    }
}

__global__ __launch_bounds__(NT)
void audio_epilogue_kernel(const float* __restrict__ b1,
                           const float* __restrict__ b2,
                           const float* __restrict__ b3,
                           const float* __restrict__ b4,
                           const float* __restrict__ b5,
                           const float* __restrict__ wd,
                           const float* __restrict__ bd,
                           float* __restrict__ out)
{
    // One CTA per 2 rows: 256 threads -> 2 x 128 outputs.
    const int tid = threadIdx.x;
    const int row = blockIdx.x * 2 + (tid >> 7);
    const int d   = tid & 127;

    const float bias = b1[0] + b2[0] + b3[0] + b4[0] + b5[0];
    const float s = g_partial[row * SPLIT + 0]
                  + g_partial[row * SPLIT + 1] + bias;

    out[(size_t)row * 128 + d] = fmaf(s, wd[d], bd[d]);
}

extern "C" void kernel_launch(void* const* d_in, const int* in_sizes, int n_in,
                              void* d_out, int out_size)
{
    // metadata order: x, w1, b1, w2, b2, w3, b3, w4, b4, w5, b5, wd, bd
    const float* x  = (const float*)d_in[0];
    const float* w1 = (const float*)d_in[1];
    const float* b1 = (const float*)d_in[2];
    const float* b2 = (const float*)d_in[4];
    const float* b3 = (const float*)d_in[6];
    const float* b4 = (const float*)d_in[8];
    const float* b5 = (const float*)d_in[10];
    const float* wd = (const float*)d_in[11];
    const float* bd = (const float*)d_in[12];
    float* out = (float*)d_out;

    dim3 gridA((B_ROWS / RPB) * SPLIT);   // 8192 CTAs (half row-pairs)
    audio_dot_kernel<<<gridA, NT>>>(x, w1);

    dim3 gridB(B_ROWS / 2);               // 4096 CTAs, 2 rows each
    audio_epilogue_kernel<<<gridB, NT>>>(b1, b2, b3, b4, b5, wd, bd, out);
}